// round 5
// baseline (speedup 1.0000x reference)
#include <cuda_runtime.h>
#include <cstdint>

// N=32, H=1024, W=1024 fp32.
// Composite filter: reference applies 2x2 stencil S (forward taps
// [[1,.5],[.5,.25]], zero pad) 4x; batch reversals cancel; S separable, so
// S^4 = 1D taps (1+0.5z)^4 = [1, 2, 1.5, 0.5, 0.0625] along H and W.
#define Wd 1024
#define Hd 1024
#define Nd 32
#define TILES 4                   // output tiles (8 rows each) per CTA
#define ROWS_OUT (8 * TILES)      // 32 output rows per CTA
#define IN_STRIDE 1032            // floats per smem row (1028 used + 4 pad)
#define CHUNK_FLOATS (8 * IN_STRIDE)
#define CH_PER_ROW 257            // 16B chunks per row (1028 floats)

__device__ __forceinline__ uint32_t smem_u32(const void* p) {
    uint32_t a;
    asm("{ .reg .u64 t; cvta.to.shared.u64 t, %1; cvt.u32.u64 %0, t; }" : "=r"(a) : "l"(p));
    return a;
}

// Load `nrows` rows of chunk c (global rows row0 + c*8 + [0,nrows)) into ring
// slot c%3. Zero-fills rows >= Hd and the 4-col right halo beyond W.
__device__ __forceinline__ void load_chunk(const float* __restrict__ img,
                                           uint32_t sbase, int row0,
                                           int c, int nrows, int tx) {
    const int total = nrows * CH_PER_ROW;
    const uint32_t slotBase = sbase + (uint32_t)((c % 3) * CHUNK_FLOATS) * 4u;
    #pragma unroll
    for (int k = 0; k < 9; k++) {
        const int idx = k * 256 + tx;
        if (idx < total) {
            const int r     = idx / CH_PER_ROW;
            const int chunk = idx - r * CH_PER_ROW;   // 0..256
            const int gr = row0 + c * 8 + r;
            const int n = (gr < Hd && chunk < 256) ? 16 : 0;   // zero-fill OOB
            const float* src = img + (size_t)min(gr, Hd - 1) * Wd + min(chunk, 255) * 4;
            const uint32_t dst = slotBase + (uint32_t)(r * IN_STRIDE + chunk * 4) * 4u;
            asm volatile("cp.async.cg.shared.global [%0], [%1], 16, %2;\n"
                         :: "r"(dst), "l"(src), "r"(n) : "memory");
        }
    }
    asm volatile("cp.async.commit_group;\n" ::: "memory");
}

__global__ __launch_bounds__(256)
void stencil4_kernel(const float* __restrict__ in, float* __restrict__ out) {
    extern __shared__ float s[];   // 3 * CHUNK_FLOATS floats = 99072 B
    const int tx = threadIdx.x;    // 0..255
    const int j  = tx << 2;        // this thread's 4 columns
    const int row0 = blockIdx.x * ROWS_OUT;
    const size_t imgOff = (size_t)blockIdx.y * (size_t)Hd * Wd;
    const float* __restrict__ img = in + imgOff;
    float* __restrict__ o = out + imgOff;
    const uint32_t sbase = smem_u32(s);

    // Prologue: chunks 0 and 1 in flight (two groups).
    load_chunk(img, sbase, row0, 0, 8, tx);
    load_chunk(img, sbase, row0, 1, 8, tx);

    #pragma unroll
    for (int t = 0; t < TILES; t++) {
        // Guard ring-slot reuse: all readers of the slot chunk t+2 overwrites
        // (chunk t-1, consumed in tile t-1) must be done.
        __syncthreads();

        if (t + 2 <= TILES) {
            // Last chunk (index TILES) is a 4-row partial: rows fully used.
            load_chunk(img, sbase, row0, t + 2, (t + 2 == TILES) ? 4 : 8, tx);
            asm volatile("cp.async.wait_group 1;\n" ::: "memory");
        } else {
            asm volatile("cp.async.wait_group 0;\n" ::: "memory");
        }
        __syncthreads();   // chunks t, t+1 visible to all threads

        // ---- Horizontal 5-tap for 12 input rows (chunks t, t+1) ----
        float h[12][4];
        #pragma unroll
        for (int r = 0; r < 12; r++) {
            const int lr = 8 * t + r;              // CTA-local input row
            const int slot = (lr >> 3) % 3;
            const float* srow = &s[slot * CHUNK_FLOATS + (lr & 7) * IN_STRIDE];
            const float4 A = *reinterpret_cast<const float4*>(srow + j);
            const float4 B = *reinterpret_cast<const float4*>(srow + j + 4);
            const float a0 = A.x, a1 = A.y, a2 = A.z, a3 = A.w;
            const float a4 = B.x, a5 = B.y, a6 = B.z, a7 = B.w;
            float v;
            v = fmaf(2.0f, a1, a0); v = fmaf(1.5f, a2, v); v = fmaf(0.5f, a3, v); h[r][0] = fmaf(0.0625f, a4, v);
            v = fmaf(2.0f, a2, a1); v = fmaf(1.5f, a3, v); v = fmaf(0.5f, a4, v); h[r][1] = fmaf(0.0625f, a5, v);
            v = fmaf(2.0f, a3, a2); v = fmaf(1.5f, a4, v); v = fmaf(0.5f, a5, v); h[r][2] = fmaf(0.0625f, a6, v);
            v = fmaf(2.0f, a4, a3); v = fmaf(1.5f, a5, v); v = fmaf(0.5f, a6, v); h[r][3] = fmaf(0.0625f, a7, v);
        }

        // ---- Vertical 5-tap + streaming stores (8 output rows) ----
        #pragma unroll
        for (int rr = 0; rr < 8; rr++) {
            float4 R;
            float v;
            v = fmaf(2.0f, h[rr+1][0], h[rr][0]); v = fmaf(1.5f, h[rr+2][0], v);
            v = fmaf(0.5f, h[rr+3][0], v);        R.x = fmaf(0.0625f, h[rr+4][0], v);
            v = fmaf(2.0f, h[rr+1][1], h[rr][1]); v = fmaf(1.5f, h[rr+2][1], v);
            v = fmaf(0.5f, h[rr+3][1], v);        R.y = fmaf(0.0625f, h[rr+4][1], v);
            v = fmaf(2.0f, h[rr+1][2], h[rr][2]); v = fmaf(1.5f, h[rr+2][2], v);
            v = fmaf(0.5f, h[rr+3][2], v);        R.z = fmaf(0.0625f, h[rr+4][2], v);
            v = fmaf(2.0f, h[rr+1][3], h[rr][3]); v = fmaf(1.5f, h[rr+2][3], v);
            v = fmaf(0.5f, h[rr+3][3], v);        R.w = fmaf(0.0625f, h[rr+4][3], v);
            __stcs(reinterpret_cast<float4*>(o + (size_t)(row0 + 8 * t + rr) * Wd + j), R);
        }
    }
}

extern "C" void kernel_launch(void* const* d_in, const int* in_sizes, int n_in,
                              void* d_out, int out_size) {
    const float* img = (const float*)d_in[0];
    float* out = (float*)d_out;
    const int smem = 3 * CHUNK_FLOATS * sizeof(float);   // 99072 B
    cudaFuncSetAttribute(stencil4_kernel,
                         cudaFuncAttributeMaxDynamicSharedMemorySize, smem);
    dim3 grid(Hd / ROWS_OUT, Nd);   // 32 x 32 = 1024 CTAs
    dim3 block(256);
    stencil4_kernel<<<grid, block, smem>>>(img, out);
}

// round 6
// speedup vs baseline: 1.0656x; 1.0656x over previous
#include <cuda_runtime.h>
#include <cstdint>

// N=32, H=1024, W=1024 fp32.
// Composite filter: reference applies 2x2 stencil S (forward taps
// [[1,.5],[.5,.25]], zero pad) 4x; batch reversals cancel; S separable, so
// S^4 = 1D taps (1+0.5z)^4 = [1, 2, 1.5, 0.5, 0.0625] along H and W.
#define Wd 1024
#define Hd 1024
#define Nd 32
#define W_TILE 512
#define H_TILE 8
#define H_IN   12                 // H_TILE + 4 halo rows
#define IN_STRIDE 520             // floats per smem row (516 used + 4 pad)
#define CH_PER_ROW 129            // 16B chunks per row (516 floats)
#define TOTAL_CH (H_IN * CH_PER_ROW)   // 1548

__device__ __forceinline__ uint32_t smem_u32(const void* p) {
    uint32_t a;
    asm("{ .reg .u64 t; cvta.to.shared.u64 t, %1; cvt.u32.u64 %0, t; }" : "=r"(a) : "l"(p));
    return a;
}

__global__ __launch_bounds__(128)
void stencil4_kernel(const float* __restrict__ in, float* __restrict__ out) {
    extern __shared__ float s[];   // H_IN * IN_STRIDE floats = 24960 B
    const int tx = threadIdx.x;    // 0..127
    const int row0 = blockIdx.x * H_TILE;
    const int c0   = blockIdx.y * W_TILE;
    const size_t imgOff = (size_t)blockIdx.z * (size_t)Hd * Wd;
    const float* __restrict__ img = in + imgOff;
    float* __restrict__ o = out + imgOff;
    const uint32_t sbase = smem_u32(s);

    // ---- Async load: 12 rows x 516 cols into smem (zero-fill OOB) ----
    #pragma unroll
    for (int k = 0; k < 13; k++) {
        const int idx = k * 128 + tx;
        if (idx < TOTAL_CH) {
            const int row   = idx / CH_PER_ROW;        // 0..11
            const int chunk = idx - row * CH_PER_ROW;  // 0..128
            const int gr = row0 + row;
            const int gc = c0 + chunk * 4;             // global col of this 16B
            const int n = (gr < Hd && gc < Wd) ? 16 : 0;   // zero-fill OOB
            const float* src = img + (size_t)min(gr, Hd - 1) * Wd + min(gc, Wd - 4);
            const uint32_t dst = sbase + (uint32_t)(row * IN_STRIDE + chunk * 4) * 4u;
            asm volatile("cp.async.cg.shared.global [%0], [%1], 16, %2;\n"
                         :: "r"(dst), "l"(src), "r"(n) : "memory");
        }
    }
    asm volatile("cp.async.commit_group;\n" ::: "memory");
    asm volatile("cp.async.wait_group 0;\n" ::: "memory");
    __syncthreads();

    // ---- Horizontal 5-tap per row from smem ----
    const int j = tx << 2;         // this thread's 4 local columns
    float h[H_IN][4];
    #pragma unroll
    for (int r = 0; r < H_IN; r++) {
        const float4 A = *reinterpret_cast<const float4*>(&s[r * IN_STRIDE + j]);
        const float4 B = *reinterpret_cast<const float4*>(&s[r * IN_STRIDE + j + 4]);
        const float a0 = A.x, a1 = A.y, a2 = A.z, a3 = A.w;
        const float a4 = B.x, a5 = B.y, a6 = B.z, a7 = B.w;
        float v;
        v = fmaf(2.0f, a1, a0); v = fmaf(1.5f, a2, v); v = fmaf(0.5f, a3, v); h[r][0] = fmaf(0.0625f, a4, v);
        v = fmaf(2.0f, a2, a1); v = fmaf(1.5f, a3, v); v = fmaf(0.5f, a4, v); h[r][1] = fmaf(0.0625f, a5, v);
        v = fmaf(2.0f, a3, a2); v = fmaf(1.5f, a4, v); v = fmaf(0.5f, a5, v); h[r][2] = fmaf(0.0625f, a6, v);
        v = fmaf(2.0f, a4, a3); v = fmaf(1.5f, a5, v); v = fmaf(0.5f, a6, v); h[r][3] = fmaf(0.0625f, a7, v);
    }

    // ---- Vertical 5-tap + streaming stores ----
    #pragma unroll
    for (int rr = 0; rr < H_TILE; rr++) {
        float4 R;
        float v;
        v = fmaf(2.0f, h[rr+1][0], h[rr][0]); v = fmaf(1.5f, h[rr+2][0], v);
        v = fmaf(0.5f, h[rr+3][0], v);        R.x = fmaf(0.0625f, h[rr+4][0], v);
        v = fmaf(2.0f, h[rr+1][1], h[rr][1]); v = fmaf(1.5f, h[rr+2][1], v);
        v = fmaf(0.5f, h[rr+3][1], v);        R.y = fmaf(0.0625f, h[rr+4][1], v);
        v = fmaf(2.0f, h[rr+1][2], h[rr][2]); v = fmaf(1.5f, h[rr+2][2], v);
        v = fmaf(0.5f, h[rr+3][2], v);        R.z = fmaf(0.0625f, h[rr+4][2], v);
        v = fmaf(2.0f, h[rr+1][3], h[rr][3]); v = fmaf(1.5f, h[rr+2][3], v);
        v = fmaf(0.5f, h[rr+3][3], v);        R.w = fmaf(0.0625f, h[rr+4][3], v);
        __stcs(reinterpret_cast<float4*>(o + (size_t)(row0 + rr) * Wd + c0 + j), R);
    }
}

extern "C" void kernel_launch(void* const* d_in, const int* in_sizes, int n_in,
                              void* d_out, int out_size) {
    const float* img = (const float*)d_in[0];
    float* out = (float*)d_out;
    const int smem = H_IN * IN_STRIDE * sizeof(float);   // 24960 B
    cudaFuncSetAttribute(stencil4_kernel,
                         cudaFuncAttributeMaxDynamicSharedMemorySize, smem);
    dim3 grid(Hd / H_TILE, Wd / W_TILE, Nd);   // 128 x 2 x 32 = 8192 CTAs
    dim3 block(128);
    stencil4_kernel<<<grid, block, smem>>>(img, out);
}

// round 7
// speedup vs baseline: 1.0694x; 1.0036x over previous
#include <cuda_runtime.h>
#include <cstdint>

// N=32, H=1024, W=1024 fp32.
// Composite filter: reference applies 2x2 stencil S (forward taps
// [[1,.5],[.5,.25]], zero pad) 4x; batch reversals cancel; S separable, so
// S^4 = 1D taps (1+0.5z)^4 = [1, 2, 1.5, 0.5, 0.0625] along H and W.
#define Wd 1024
#define Hd 1024
#define Nd 32
#define H_TILE 8
#define H_IN   12                  // H_TILE + 4 halo rows
#define W_WARP 128                 // output cols per warp
#define IN_STRIDE 136              // floats per smem row (132 used + pad -> 34 chunks)
#define CH_PER_ROW 34              // 16B chunks per smem row
#define WARP_FLOATS (H_IN * IN_STRIDE)   // 1632 floats = 6528 B per warp
#define TOTAL_CH (H_IN * CH_PER_ROW)     // 408 chunks per warp tile

__device__ __forceinline__ uint32_t smem_u32(const void* p) {
    uint32_t a;
    asm("{ .reg .u64 t; cvta.to.shared.u64 t, %1; cvt.u32.u64 %0, t; }" : "=r"(a) : "l"(p));
    return a;
}

__global__ __launch_bounds__(256)
void stencil4_kernel(const float* __restrict__ in, float* __restrict__ out) {
    extern __shared__ float s[];     // 8 warps * 6528 B = 52224 B
    const int tx   = threadIdx.x;
    const int wid  = tx >> 5;        // warp 0..7 -> 128-col segment
    const int lane = tx & 31;
    const int row0 = blockIdx.x * H_TILE;
    const int c0   = wid * W_WARP;   // global col base of this warp's tile
    const size_t imgOff = (size_t)blockIdx.y * (size_t)Hd * Wd;
    const float* __restrict__ img = in + imgOff;
    float* __restrict__ o = out + imgOff;

    float* sw = s + wid * WARP_FLOATS;
    const uint32_t swb = smem_u32(sw);

    // ---- Per-warp async load: 12 rows x 132(+pad) cols, zero-fill OOB ----
    #pragma unroll
    for (int k = 0; k < 13; k++) {
        const int idx = k * 32 + lane;
        if (idx < TOTAL_CH) {
            const int row = idx / CH_PER_ROW;          // 0..11
            const int ch  = idx - row * CH_PER_ROW;    // 0..33
            const int gr  = row0 + row;
            const int gc  = c0 + ch * 4;
            const int n = (gr < Hd && gc < Wd) ? 16 : 0;   // zero-fill OOB
            const float* src = img + (size_t)min(gr, Hd - 1) * Wd + min(gc, Wd - 4);
            const uint32_t dst = swb + (uint32_t)(row * IN_STRIDE + ch * 4) * 4u;
            asm volatile("cp.async.cg.shared.global [%0], [%1], 16, %2;\n"
                         :: "r"(dst), "l"(src), "r"(n) : "memory");
        }
    }
    asm volatile("cp.async.commit_group;\n" ::: "memory");
    asm volatile("cp.async.wait_group 0;\n" ::: "memory");   // only THIS warp's loads
    __syncwarp();

    // ---- Horizontal 5-tap per row from this warp's smem tile ----
    const int j = lane << 2;         // local cols [j, j+3]
    float h[H_IN][4];
    #pragma unroll
    for (int r = 0; r < H_IN; r++) {
        const float4 A = *reinterpret_cast<const float4*>(&sw[r * IN_STRIDE + j]);
        const float4 B = *reinterpret_cast<const float4*>(&sw[r * IN_STRIDE + j + 4]);
        const float a0 = A.x, a1 = A.y, a2 = A.z, a3 = A.w;
        const float a4 = B.x, a5 = B.y, a6 = B.z, a7 = B.w;
        float v;
        v = fmaf(2.0f, a1, a0); v = fmaf(1.5f, a2, v); v = fmaf(0.5f, a3, v); h[r][0] = fmaf(0.0625f, a4, v);
        v = fmaf(2.0f, a2, a1); v = fmaf(1.5f, a3, v); v = fmaf(0.5f, a4, v); h[r][1] = fmaf(0.0625f, a5, v);
        v = fmaf(2.0f, a3, a2); v = fmaf(1.5f, a4, v); v = fmaf(0.5f, a5, v); h[r][2] = fmaf(0.0625f, a6, v);
        v = fmaf(2.0f, a4, a3); v = fmaf(1.5f, a5, v); v = fmaf(0.5f, a6, v); h[r][3] = fmaf(0.0625f, a7, v);
    }

    // ---- Vertical 5-tap + streaming stores ----
    #pragma unroll
    for (int rr = 0; rr < H_TILE; rr++) {
        float4 R;
        float v;
        v = fmaf(2.0f, h[rr+1][0], h[rr][0]); v = fmaf(1.5f, h[rr+2][0], v);
        v = fmaf(0.5f, h[rr+3][0], v);        R.x = fmaf(0.0625f, h[rr+4][0], v);
        v = fmaf(2.0f, h[rr+1][1], h[rr][1]); v = fmaf(1.5f, h[rr+2][1], v);
        v = fmaf(0.5f, h[rr+3][1], v);        R.y = fmaf(0.0625f, h[rr+4][1], v);
        v = fmaf(2.0f, h[rr+1][2], h[rr][2]); v = fmaf(1.5f, h[rr+2][2], v);
        v = fmaf(0.5f, h[rr+3][2], v);        R.z = fmaf(0.0625f, h[rr+4][2], v);
        v = fmaf(2.0f, h[rr+1][3], h[rr][3]); v = fmaf(1.5f, h[rr+2][3], v);
        v = fmaf(0.5f, h[rr+3][3], v);        R.w = fmaf(0.0625f, h[rr+4][3], v);
        __stcs(reinterpret_cast<float4*>(o + (size_t)(row0 + rr) * Wd + c0 + j), R);
    }
}

extern "C" void kernel_launch(void* const* d_in, const int* in_sizes, int n_in,
                              void* d_out, int out_size) {
    const float* img = (const float*)d_in[0];
    float* out = (float*)d_out;
    const int smem = 8 * WARP_FLOATS * sizeof(float);   // 52224 B
    cudaFuncSetAttribute(stencil4_kernel,
                         cudaFuncAttributeMaxDynamicSharedMemorySize, smem);
    dim3 grid(Hd / H_TILE, Nd);     // 128 x 32 = 4096 CTAs, each full-width
    dim3 block(256);
    stencil4_kernel<<<grid, block, smem>>>(img, out);
}

// round 8
// speedup vs baseline: 1.0977x; 1.0265x over previous
#include <cuda_runtime.h>
#include <cstdint>

// N=32, H=1024, W=1024 fp32.
// Composite filter: reference applies 2x2 stencil S (forward taps
// [[1,.5],[.5,.25]], zero pad) 4x; batch reversals cancel; S separable, so
// S^4 = 1D taps (1+0.5z)^4 = [1, 2, 1.5, 0.5, 0.0625] along H and W.
#define Wd 1024
#define Hd 1024
#define Nd 32
#define H_TILE 8
#define H_IN   12                  // H_TILE + 4 halo rows
#define W_WARP 128                 // output cols per warp
#define IN_STRIDE 136              // floats per smem row (132 used + pad)
#define CH_PER_ROW 34              // 16B chunks per smem row
#define WARP_FLOATS (H_IN * IN_STRIDE)   // 1632 floats = 6528 B per warp
#define TOTAL_CH (H_IN * CH_PER_ROW)     // 408 chunks per warp tile

__device__ __forceinline__ uint32_t smem_u32(const void* p) {
    uint32_t a;
    asm("{ .reg .u64 t; cvta.to.shared.u64 t, %1; cvt.u32.u64 %0, t; }" : "=r"(a) : "l"(p));
    return a;
}

__global__ __launch_bounds__(256)
void stencil4_kernel(const float* __restrict__ in, float* __restrict__ out) {
    extern __shared__ float s[];     // 8 warps * 6528 B = 52224 B
    const int tx   = threadIdx.x;
    const int wid  = tx >> 5;        // warp 0..7 -> 128-col segment
    const int lane = tx & 31;
    const int row0 = blockIdx.x * H_TILE;
    const int c0   = wid * W_WARP;   // global col base of this warp's tile
    const size_t imgOff = (size_t)blockIdx.y * (size_t)Hd * Wd;
    const float* __restrict__ img = in + imgOff;
    float* __restrict__ o = out + imgOff;

    float* sw = s + wid * WARP_FLOATS;
    const uint32_t swb = smem_u32(sw);

    // L2 policy: keep input lines resident (evict_last) — the 128 MB input
    // nearly fits the 126 MB L2 across graph replays; writes are streamed
    // (__stcs, evict-first) so they do not churn the input working set.
    uint64_t pol;
    asm("createpolicy.fractional.L2::evict_last.b64 %0, 1.0;" : "=l"(pol));

    // ---- Per-warp async load: 12 rows x 132(+pad) cols, zero-fill OOB ----
    #pragma unroll
    for (int k = 0; k < 13; k++) {
        const int idx = k * 32 + lane;
        if (idx < TOTAL_CH) {
            const int row = idx / CH_PER_ROW;          // 0..11
            const int ch  = idx - row * CH_PER_ROW;    // 0..33
            const int gr  = row0 + row;
            const int gc  = c0 + ch * 4;
            const int n = (gr < Hd && gc < Wd) ? 16 : 0;   // zero-fill OOB
            const float* src = img + (size_t)min(gr, Hd - 1) * Wd + min(gc, Wd - 4);
            const uint32_t dst = swb + (uint32_t)(row * IN_STRIDE + ch * 4) * 4u;
            asm volatile("cp.async.cg.shared.global.L2::cache_hint [%0], [%1], 16, %2, %3;\n"
                         :: "r"(dst), "l"(src), "r"(n), "l"(pol) : "memory");
        }
    }
    asm volatile("cp.async.commit_group;\n" ::: "memory");
    asm volatile("cp.async.wait_group 0;\n" ::: "memory");   // only THIS warp's loads
    __syncwarp();

    // ---- Horizontal 5-tap per row from this warp's smem tile ----
    const int j = lane << 2;         // local cols [j, j+3]
    float h[H_IN][4];
    #pragma unroll
    for (int r = 0; r < H_IN; r++) {
        const float4 A = *reinterpret_cast<const float4*>(&sw[r * IN_STRIDE + j]);
        const float4 B = *reinterpret_cast<const float4*>(&sw[r * IN_STRIDE + j + 4]);
        const float a0 = A.x, a1 = A.y, a2 = A.z, a3 = A.w;
        const float a4 = B.x, a5 = B.y, a6 = B.z, a7 = B.w;
        float v;
        v = fmaf(2.0f, a1, a0); v = fmaf(1.5f, a2, v); v = fmaf(0.5f, a3, v); h[r][0] = fmaf(0.0625f, a4, v);
        v = fmaf(2.0f, a2, a1); v = fmaf(1.5f, a3, v); v = fmaf(0.5f, a4, v); h[r][1] = fmaf(0.0625f, a5, v);
        v = fmaf(2.0f, a3, a2); v = fmaf(1.5f, a4, v); v = fmaf(0.5f, a5, v); h[r][2] = fmaf(0.0625f, a6, v);
        v = fmaf(2.0f, a4, a3); v = fmaf(1.5f, a5, v); v = fmaf(0.5f, a6, v); h[r][3] = fmaf(0.0625f, a7, v);
    }

    // ---- Vertical 5-tap + streaming stores ----
    #pragma unroll
    for (int rr = 0; rr < H_TILE; rr++) {
        float4 R;
        float v;
        v = fmaf(2.0f, h[rr+1][0], h[rr][0]); v = fmaf(1.5f, h[rr+2][0], v);
        v = fmaf(0.5f, h[rr+3][0], v);        R.x = fmaf(0.0625f, h[rr+4][0], v);
        v = fmaf(2.0f, h[rr+1][1], h[rr][1]); v = fmaf(1.5f, h[rr+2][1], v);
        v = fmaf(0.5f, h[rr+3][1], v);        R.y = fmaf(0.0625f, h[rr+4][1], v);
        v = fmaf(2.0f, h[rr+1][2], h[rr][2]); v = fmaf(1.5f, h[rr+2][2], v);
        v = fmaf(0.5f, h[rr+3][2], v);        R.z = fmaf(0.0625f, h[rr+4][2], v);
        v = fmaf(2.0f, h[rr+1][3], h[rr][3]); v = fmaf(1.5f, h[rr+2][3], v);
        v = fmaf(0.5f, h[rr+3][3], v);        R.w = fmaf(0.0625f, h[rr+4][3], v);
        __stcs(reinterpret_cast<float4*>(o + (size_t)(row0 + rr) * Wd + c0 + j), R);
    }
}

extern "C" void kernel_launch(void* const* d_in, const int* in_sizes, int n_in,
                              void* d_out, int out_size) {
    const float* img = (const float*)d_in[0];
    float* out = (float*)d_out;
    const int smem = 8 * WARP_FLOATS * sizeof(float);   // 52224 B
    cudaFuncSetAttribute(stencil4_kernel,
                         cudaFuncAttributeMaxDynamicSharedMemorySize, smem);
    dim3 grid(Hd / H_TILE, Nd);     // 128 x 32 = 4096 CTAs, each full-width
    dim3 block(256);
    stencil4_kernel<<<grid, block, smem>>>(img, out);
}